// round 12
// baseline (speedup 1.0000x reference)
#include <cuda_runtime.h>
#include <cstdint>

#define FULLMASK 0xFFFFFFFFu

static constexpr int B_ = 8, C_ = 64, H_ = 512, W_ = 512, NSEG = 512;
static constexpr int WARPS = 4, THREADS = 128, CPW = 4;   // channels per warp
static constexpr int CGROUPS = C_ / (WARPS * CPW);        // 4 channel groups
static constexpr int SPLITS = 17, ROWS = 30;              // 17*30 = 510 interior rows exactly
static constexpr size_t PLANE = (size_t)H_ * W_;

__device__ __forceinline__ unsigned fmap(float f) {
    // order-preserving fp32 -> uint32 (monotone under unsigned compare)
    unsigned u = __float_as_uint(f);
    return (u & 0x80000000u) ? ~u : (u | 0x80000000u);
}

__global__ void __launch_bounds__(256) sf_init_kernel(unsigned* __restrict__ out, int n) {
    int i = blockIdx.x * blockDim.x + threadIdx.x;
    if (i < n) out[i] = 0x007FFFFFu;   // fmap(-inf)
}

__global__ void __launch_bounds__(256) sf_fini_kernel(unsigned* __restrict__ out, int n) {
    int i = blockIdx.x * blockDim.x + threadIdx.x;
    if (i < n) {
        unsigned u = out[i];
        float f = (u & 0x80000000u) ? __uint_as_float(u ^ 0x80000000u)
                                    : __uint_as_float(~u);
        if (!isfinite(f)) f = 0.0f;    // empty segments (-inf) -> 0, like reference
        out[i] = __float_as_uint(f);
    }
}

__device__ __forceinline__ float f4c(const float4& v, int j) {
    return j == 0 ? v.x : (j == 1 ? v.y : (j == 2 ? v.z : v.w));
}

__global__ void __launch_bounds__(THREADS) sf_segmax_kernel(
    const float* __restrict__ feats,
    const int* __restrict__ mask,     // JAX x64-disabled: "int64" randint is int32
    unsigned* __restrict__ out)
{
    // 32KB bins + 2x2KB spk + 2x2KB peers = 40KB static shared
    __shared__ float4   binsv[WARPS * NSEG];   // float4-aligned warp-private bins
    __shared__ int      spk[2][W_];            // seg(9) | cnt(6)<<9 | maxc(6)<<15 | leader<<21
    __shared__ unsigned spr[2][W_];            // peers mask

    const int tid  = threadIdx.x;
    const int lane = tid & 31;
    const int wid  = tid >> 5;

    const int bid    = blockIdx.x;
    const int split  = bid % SPLITS;
    const int cgroup = (bid / SPLITS) % CGROUPS;
    const int b      = bid / (SPLITS * CGROUPS);

    const int r0 = 1 + split * ROWS;           // rows [r0, r0+30), within [1, 511)
    const int cbase = cgroup * (WARPS * CPW) + wid * CPW;

    const float NEG_INF = __int_as_float(0xff800000);
    const float4 NEG4 = make_float4(NEG_INF, NEG_INF, NEG_INF, NEG_INF);

    for (int i = tid; i < WARPS * NSEG; i += THREADS) binsv[i] = NEG4;

    float4* wb = binsv + wid * NSEG;
    const float* f0 = feats + ((size_t)(b * C_ + cbase)) * PLANE;
    const int*   mb = mask + (size_t)b * PLANE;

    __syncthreads();

    #pragma unroll 1
    for (int e = 0; e < ROWS / 2; ++e) {
        const int r = r0 + e * 2;

        // ---- stage 2 rows of conflict info; warp `wid` covers its 128-col block.
        // lane l holds cols 128*wid + 4l + {0..3} via one int4 LDG; for each sub
        // j the warp's 32 lanes are exactly the strided conflict group.
        #pragma unroll
        for (int rr = 0; rr < 2; ++rr) {
            const int4 m = ((const int4*)(mb + (size_t)(r + rr) * W_ + 128 * wid))[lane];
            const int mj[4] = { m.x, m.y, m.z, m.w };
            #pragma unroll
            for (int j = 0; j < 4; ++j) {
                int seg = mj[j] & (NSEG - 1);
                unsigned peers = __match_any_sync(FULLMASK, seg);
                int cnt    = __popc(peers);
                int maxc   = __reduce_max_sync(FULLMASK, cnt);
                int leader = (peers & ((1u << lane) - 1u)) == 0u;  // rank 0
                spk[rr][(wid * 4 + j) * 32 + lane] =
                    seg | (cnt << 9) | (maxc << 15) | (leader << 21);
                spr[rr][(wid * 4 + j) * 32 + lane] = peers;
            }
        }
        __syncthreads();

        #pragma unroll 1
        for (int rr = 0; rr < 2; ++rr) {
            const float* frow = f0 + (size_t)(r + rr) * W_;

            float4 cur[4], nxt[4];
            #pragma unroll
            for (int c = 0; c < 4; ++c)
                cur[c] = ((const float4*)(frow + c * PLANE))[lane];

            #pragma unroll
            for (int p = 0; p < 4; ++p) {
                if (p < 3) {
                    #pragma unroll
                    for (int c = 0; c < 4; ++c)
                        nxt[c] = ((const float4*)(frow + (p + 1) * 128 + c * PLANE))[lane];
                }
                #pragma unroll
                for (int j = 0; j < 4; ++j) {
                    // 4-channel value vector for col = 128p + 4*lane + j
                    float4 u = make_float4(f4c(cur[0], j), f4c(cur[1], j),
                                           f4c(cur[2], j), f4c(cur[3], j));
                    if ((p == 0 && j == 0 && lane == 0) ||
                        (p == 3 && j == 3 && lane == 31))
                        u = NEG4;                       // crop cols 0 and 511

                    const int idx  = (p * 4 + j) * 32 + lane;
                    const int info = spk[rr][idx];      // conflict-free LDS
                    const int seg    = info & (NSEG - 1);
                    const int cnt    = (info >> 9) & 63;
                    const int maxc   = (info >> 15) & 63;   // warp-uniform
                    const bool leader = (info >> 21) & 1;

                    if (maxc > 1) {                     // warp-uniform branch
                        const unsigned peers = spr[rr][idx];
                        // leaders fold duplicate lanes' values via shfl;
                        // non-participants self-shfl (harmless fmax w/ self)
                        #pragma unroll 1
                        for (int k = 1; k < maxc; ++k) {
                            bool act = leader && (k < cnt);
                            int  s   = act ? (int)__fns(peers, 0, k + 1) : lane;
                            u.x = fmaxf(u.x, __shfl_sync(FULLMASK, u.x, s));
                            u.y = fmaxf(u.y, __shfl_sync(FULLMASK, u.y, s));
                            u.z = fmaxf(u.z, __shfl_sync(FULLMASK, u.z, s));
                            u.w = fmaxf(u.w, __shfl_sync(FULLMASK, u.w, s));
                        }
                    }
                    // only leaders write; leader segs are distinct within the
                    // warp (and when maxc==1 every lane is a leader) -> no race
                    if (leader) {
                        float4 curb = wb[seg];
                        curb.x = fmaxf(curb.x, u.x);
                        curb.y = fmaxf(curb.y, u.y);
                        curb.z = fmaxf(curb.z, u.z);
                        curb.w = fmaxf(curb.w, u.w);
                        wb[seg] = curb;
                    }
                }
                #pragma unroll
                for (int c = 0; c < 4; ++c) cur[c] = nxt[c];
            }
        }
        __syncthreads();   // protect spk/spr before next epoch's staging
    }

    // merge warp-private bins into global output via ordered-uint atomicMax
    unsigned* ob = out + ((size_t)(b * C_ + cbase)) * NSEG;
    for (int s = lane; s < NSEG; s += 32) {
        float4 v = wb[s];
        atomicMax(ob + 0 * NSEG + s, fmap(v.x));
        atomicMax(ob + 1 * NSEG + s, fmap(v.y));
        atomicMax(ob + 2 * NSEG + s, fmap(v.z));
        atomicMax(ob + 3 * NSEG + s, fmap(v.w));
    }
}

extern "C" void kernel_launch(void* const* d_in, const int* in_sizes, int n_in,
                              void* d_out, int out_size) {
    (void)in_sizes; (void)n_in;
    const float* feats = (const float*)d_in[0];
    const int*   mask  = (const int*)d_in[1];
    unsigned*    out   = (unsigned*)d_out;

    const int n = out_size;   // 8*64*512 = 262144

    sf_init_kernel<<<(n + 255) / 256, 256>>>(out, n);
    sf_segmax_kernel<<<B_ * CGROUPS * SPLITS, THREADS>>>(feats, mask, out);
    sf_fini_kernel<<<(n + 255) / 256, 256>>>(out, n);
}

// round 14
// speedup vs baseline: 1.4459x; 1.4459x over previous
#include <cuda_runtime.h>
#include <cstdint>

#define FULLMASK 0xFFFFFFFFu

static constexpr int B_ = 8, C_ = 64, H_ = 512, W_ = 512, NSEG = 512;
static constexpr int WARPS = 4, THREADS = 128, CPW = 4;   // channels per warp
static constexpr int CGROUPS = C_ / (WARPS * CPW);        // 4 channel groups
static constexpr int SPLITS = 27, ROWS = 19;              // 27*19=513 >= 510 interior rows
static constexpr size_t PLANE = (size_t)H_ * W_;

__device__ __forceinline__ unsigned fmap(float f) {
    // order-preserving fp32 -> uint32 (monotone under unsigned compare)
    unsigned u = __float_as_uint(f);
    return (u & 0x80000000u) ? ~u : (u | 0x80000000u);
}

__global__ void __launch_bounds__(256) sf_init_kernel(unsigned* __restrict__ out, int n) {
    int i = blockIdx.x * blockDim.x + threadIdx.x;
    if (i < n) out[i] = 0x007FFFFFu;   // fmap(-inf)
}

__global__ void __launch_bounds__(256) sf_fini_kernel(unsigned* __restrict__ out, int n) {
    int i = blockIdx.x * blockDim.x + threadIdx.x;
    if (i < n) {
        unsigned u = out[i];
        float f = (u & 0x80000000u) ? __uint_as_float(u ^ 0x80000000u)
                                    : __uint_as_float(~u);
        if (!isfinite(f)) f = 0.0f;    // empty segments (-inf) -> 0, like reference
        out[i] = __float_as_uint(f);
    }
}

__device__ __forceinline__ float f4c(const float4& v, int j) {
    // component select; j is compile-time constant after unrolling
    return j == 0 ? v.x : (j == 1 ? v.y : (j == 2 ? v.z : v.w));
}

__global__ void __launch_bounds__(THREADS) sf_segmax_kernel(
    const float* __restrict__ feats,
    const int* __restrict__ mask,     // JAX x64-disabled: "int64" randint is int32
    unsigned* __restrict__ out)
{
    // 32KB bins + 2KB packed conflict info = 34KB static shared (6 CTAs/SM)
    __shared__ float4 binsv[WARPS * NSEG];     // float4-aligned warp-private bins
    // spk[(p*4+j)*32 + lane] for strided col group {128p + 4*lane + j}
    __shared__ int    spk[W_];   // seg(9b) | rank(5b)<<10 | maxcnt(6b)<<15

    const int tid  = threadIdx.x;
    const int lane = tid & 31;
    const int wid  = tid >> 5;

    const int bid    = blockIdx.x;
    const int split  = bid % SPLITS;
    const int cgroup = (bid / SPLITS) % CGROUPS;
    const int b      = bid / (SPLITS * CGROUPS);

    const int r0 = 1 + split * ROWS;
    const int r1 = min(r0 + ROWS, H_ - 1);
    const int cbase = cgroup * (WARPS * CPW) + wid * CPW;

    const float NEG_INF = __int_as_float(0xff800000);
    const float4 NEG4 = make_float4(NEG_INF, NEG_INF, NEG_INF, NEG_INF);

    // init warp-private bins to -inf
    for (int i = tid; i < WARPS * NSEG; i += THREADS) binsv[i] = NEG4;

    float4* wb = binsv + wid * NSEG;           // [NSEG] float4 (4 channels)
    const float* f0 = feats + ((size_t)(b * C_ + cbase)) * PLANE;
    const int*   mb = mask + (size_t)b * PLANE;

    __syncthreads();

    #pragma unroll 1
    for (int r = r0; r < r1; ++r) {
        // ---- stage conflict info: warp `wid` covers block `wid` (128 cols) ----
        // lane l holds cols 128*wid + 4l + {0,1,2,3} via one int4 LDG; for each
        // sub j, the warp's 32 lanes are exactly the strided conflict group.
        {
            const int4 m = ((const int4*)(mb + (size_t)r * W_ + 128 * wid))[lane];
            const int mj[4] = { m.x, m.y, m.z, m.w };
            #pragma unroll
            for (int j = 0; j < 4; ++j) {
                int seg = mj[j] & (NSEG - 1);
                unsigned peers = __match_any_sync(FULLMASK, seg);
                int rank = __popc(peers & ((1u << lane) - 1u));
                int cnt  = __popc(peers);
                int maxc = __reduce_max_sync(FULLMASK, cnt);
                spk[(wid * 4 + j) * 32 + lane] = seg | (rank << 10) | (maxc << 15);
            }
        }
        __syncthreads();

        const float* frow = f0 + (size_t)r * W_;

        // ---- 4 blocks of 128 cols, double-buffered LDG.128 per channel ----
        float4 cur[4], nxt[4];
        #pragma unroll
        for (int c = 0; c < 4; ++c)
            cur[c] = ((const float4*)(frow + c * PLANE))[lane];

        #pragma unroll
        for (int p = 0; p < 4; ++p) {
            if (p < 3) {
                #pragma unroll
                for (int c = 0; c < 4; ++c)
                    nxt[c] = ((const float4*)(frow + (p + 1) * 128 + c * PLANE))[lane];
            }
            #pragma unroll
            for (int j = 0; j < 4; ++j) {
                // 4-channel value vector for col = 128p + 4*lane + j
                float4 u = make_float4(f4c(cur[0], j), f4c(cur[1], j),
                                       f4c(cur[2], j), f4c(cur[3], j));
                // crop cols 0 and 511
                if ((p == 0 && j == 0 && lane == 0) ||
                    (p == 3 && j == 3 && lane == 31))
                    u = NEG4;

                int info = spk[(p * 4 + j) * 32 + lane];   // conflict-free LDS
                int seg  = info & (NSEG - 1);
                int rank = (info >> 10) & 31;
                int maxc = (info >> 15) & 63;              // warp-uniform

                if (maxc == 1) {
                    // all 32 segs distinct: concurrent RMW is race-free,
                    // zero syncwarps
                    float4 curb = wb[seg];
                    curb.x = fmaxf(curb.x, u.x);
                    curb.y = fmaxf(curb.y, u.y);
                    curb.z = fmaxf(curb.z, u.z);
                    curb.w = fmaxf(curb.w, u.w);
                    wb[seg] = curb;
                } else {
                    // rank-serialized race-free RMW; syncwarp only BETWEEN
                    // passes (serializes under ITS, blocks k-loop collapse)
                    #pragma unroll 1
                    for (int k = 0; k < maxc; ++k) {
                        if (k) __syncwarp();
                        if (rank == k) {
                            float4 curb = wb[seg];
                            curb.x = fmaxf(curb.x, u.x);
                            curb.y = fmaxf(curb.y, u.y);
                            curb.z = fmaxf(curb.z, u.z);
                            curb.w = fmaxf(curb.w, u.w);
                            wb[seg] = curb;
                        }
                    }
                }
            }
            #pragma unroll
            for (int c = 0; c < 4; ++c) cur[c] = nxt[c];
        }
        __syncthreads();   // protect spk before next row's staging
    }

    // merge warp-private bins into global output via ordered-uint atomicMax
    unsigned* ob = out + ((size_t)(b * C_ + cbase)) * NSEG;
    for (int s = lane; s < NSEG; s += 32) {
        float4 v = wb[s];
        atomicMax(ob + 0 * NSEG + s, fmap(v.x));
        atomicMax(ob + 1 * NSEG + s, fmap(v.y));
        atomicMax(ob + 2 * NSEG + s, fmap(v.z));
        atomicMax(ob + 3 * NSEG + s, fmap(v.w));
    }
}

extern "C" void kernel_launch(void* const* d_in, const int* in_sizes, int n_in,
                              void* d_out, int out_size) {
    (void)in_sizes; (void)n_in;
    const float* feats = (const float*)d_in[0];
    const int*   mask  = (const int*)d_in[1];
    unsigned*    out   = (unsigned*)d_out;

    const int n = out_size;   // 8*64*512 = 262144

    sf_init_kernel<<<(n + 255) / 256, 256>>>(out, n);
    sf_segmax_kernel<<<B_ * CGROUPS * SPLITS, THREADS>>>(feats, mask, out);
    sf_fini_kernel<<<(n + 255) / 256, 256>>>(out, n);
}

// round 16
// speedup vs baseline: 1.5224x; 1.0529x over previous
#include <cuda_runtime.h>
#include <cstdint>

#define FULLMASK 0xFFFFFFFFu

static constexpr int B_ = 8, C_ = 64, H_ = 512, W_ = 512, NSEG = 512;
static constexpr int WARPS = 4, THREADS = 128, CPW = 4;   // channels per warp
static constexpr int CGROUPS = C_ / (WARPS * CPW);        // 4 channel groups
static constexpr int SPLITS = 27, ROWS = 19;              // 27*19=513 >= 510 interior rows
static constexpr int IROWS = 510;                         // interior rows
static constexpr size_t PLANE = (size_t)H_ * W_;

// packed conflict info: seg(9b) | rank(5b)<<10 | maxc(6b)<<15
// layout: d_spkg[((b*IROWS + ri)*16 + g)*32 + lane], group g covers
// cols {128*(g/4) + 4*lane + (g%4)}
__device__ int d_spkg[(size_t)B_ * IROWS * 16 * 32];      // 8.36 MB scratch

__device__ __forceinline__ unsigned fmap(float f) {
    // order-preserving fp32 -> uint32 (monotone under unsigned compare)
    unsigned u = __float_as_uint(f);
    return (u & 0x80000000u) ? ~u : (u | 0x80000000u);
}

__global__ void __launch_bounds__(256) sf_init_kernel(unsigned* __restrict__ out, int n) {
    int i = blockIdx.x * blockDim.x + threadIdx.x;
    if (i < n) out[i] = 0x007FFFFFu;   // fmap(-inf)
}

__global__ void __launch_bounds__(256) sf_fini_kernel(unsigned* __restrict__ out, int n) {
    int i = blockIdx.x * blockDim.x + threadIdx.x;
    if (i < n) {
        unsigned u = out[i];
        float f = (u & 0x80000000u) ? __uint_as_float(u ^ 0x80000000u)
                                    : __uint_as_float(~u);
        if (!isfinite(f)) f = 0.0f;    // empty segments (-inf) -> 0, like reference
        out[i] = __float_as_uint(f);
    }
}

// Pre-pass: compute conflict info once per (batch,row,group) — removes the
// 4x-redundant match work and all staging/barriers from the main kernel.
// One warp handles one (b, ri, blk): int4 mask load, 4 match groups, 4 STG.
__global__ void __launch_bounds__(256) sf_prep_kernel(const int* __restrict__ mask) {
    const int lane = threadIdx.x & 31;
    const int w    = blockIdx.x * 8 + (threadIdx.x >> 5);  // global warp id
    const int blk  = w & 3;
    const int ri   = (w >> 2) % IROWS;
    const int b    = w / (4 * IROWS);
    if (b >= B_) return;

    const int4 m = ((const int4*)(mask + (size_t)b * PLANE
                                  + (size_t)(ri + 1) * W_ + 128 * blk))[lane];
    const int mj[4] = { m.x, m.y, m.z, m.w };
    int* dst = d_spkg + (((size_t)(b * IROWS + ri) * 16) + blk * 4) * 32 + lane;
    #pragma unroll
    for (int j = 0; j < 4; ++j) {
        int seg = mj[j] & (NSEG - 1);
        unsigned peers = __match_any_sync(FULLMASK, seg);
        int rank = __popc(peers & ((1u << lane) - 1u));
        int cnt  = __popc(peers);
        int maxc = __reduce_max_sync(FULLMASK, cnt);
        dst[j * 32] = seg | (rank << 10) | (maxc << 15);
    }
}

__device__ __forceinline__ float f4c(const float4& v, int j) {
    // component select; j is compile-time constant after unrolling
    return j == 0 ? v.x : (j == 1 ? v.y : (j == 2 ? v.z : v.w));
}

__global__ void __launch_bounds__(THREADS) sf_segmax_kernel(
    const float* __restrict__ feats,
    unsigned* __restrict__ out)
{
    // only bins in smem now: 32KB -> up to 7 CTAs/SM
    __shared__ float4 binsv[WARPS * NSEG];     // float4-aligned warp-private bins

    const int tid  = threadIdx.x;
    const int lane = tid & 31;
    const int wid  = tid >> 5;

    const int bid    = blockIdx.x;
    const int split  = bid % SPLITS;
    const int cgroup = (bid / SPLITS) % CGROUPS;
    const int b      = bid / (SPLITS * CGROUPS);

    const int r0 = 1 + split * ROWS;
    const int r1 = min(r0 + ROWS, H_ - 1);
    const int cbase = cgroup * (WARPS * CPW) + wid * CPW;

    const float NEG_INF = __int_as_float(0xff800000);
    const float4 NEG4 = make_float4(NEG_INF, NEG_INF, NEG_INF, NEG_INF);

    // init warp-private bins to -inf
    for (int i = tid; i < WARPS * NSEG; i += THREADS) binsv[i] = NEG4;

    float4* wb = binsv + wid * NSEG;           // [NSEG] float4 (4 channels)
    const float* f0 = feats + ((size_t)(b * C_ + cbase)) * PLANE;

    __syncthreads();                           // bins ready (only barrier)

    #pragma unroll 1
    for (int r = r0; r < r1; ++r) {
        const float* frow = f0 + (size_t)r * W_;
        const int*   srow = d_spkg + ((size_t)(b * IROWS + (r - 1)) * 16) * 32;

        // block 0 prefetch: 4 feature LDG.128 + 4 spk LDG.32, all independent
        float4 cur[4], nxt[4];
        int icur[4], inxt[4];
        #pragma unroll
        for (int c = 0; c < 4; ++c)
            cur[c] = ((const float4*)(frow + c * PLANE))[lane];
        #pragma unroll
        for (int j = 0; j < 4; ++j)
            icur[j] = __ldg(srow + j * 32 + lane);

        #pragma unroll
        for (int p = 0; p < 4; ++p) {
            if (p < 3) {
                #pragma unroll
                for (int c = 0; c < 4; ++c)
                    nxt[c] = ((const float4*)(frow + (p + 1) * 128 + c * PLANE))[lane];
                #pragma unroll
                for (int j = 0; j < 4; ++j)
                    inxt[j] = __ldg(srow + ((p + 1) * 4 + j) * 32 + lane);
            }
            #pragma unroll
            for (int j = 0; j < 4; ++j) {
                // 4-channel value vector for col = 128p + 4*lane + j
                float4 u = make_float4(f4c(cur[0], j), f4c(cur[1], j),
                                       f4c(cur[2], j), f4c(cur[3], j));
                // crop cols 0 and 511
                if ((p == 0 && j == 0 && lane == 0) ||
                    (p == 3 && j == 3 && lane == 31))
                    u = NEG4;

                const int info = icur[j];
                const int seg  = info & (NSEG - 1);
                const int rank = (info >> 10) & 31;
                const int maxc = (info >> 15) & 63;        // warp-uniform

                // rank-serialized race-free RMW (validated R11 form):
                // pass k writes only rank-k lanes; __syncwarp serializes
                // passes under ITS and blocks k-loop collapse.
                #pragma unroll 1
                for (int k = 0; k < maxc; ++k) {
                    if (rank == k) {
                        float4 curb = wb[seg];
                        curb.x = fmaxf(curb.x, u.x);
                        curb.y = fmaxf(curb.y, u.y);
                        curb.z = fmaxf(curb.z, u.z);
                        curb.w = fmaxf(curb.w, u.w);
                        wb[seg] = curb;
                    }
                    __syncwarp();
                }
            }
            #pragma unroll
            for (int c = 0; c < 4; ++c) cur[c] = nxt[c];
            #pragma unroll
            for (int j = 0; j < 4; ++j) icur[j] = inxt[j];
        }
    }

    // merge warp-private bins into global output via ordered-uint atomicMax
    unsigned* ob = out + ((size_t)(b * C_ + cbase)) * NSEG;
    for (int s = lane; s < NSEG; s += 32) {
        float4 v = wb[s];
        atomicMax(ob + 0 * NSEG + s, fmap(v.x));
        atomicMax(ob + 1 * NSEG + s, fmap(v.y));
        atomicMax(ob + 2 * NSEG + s, fmap(v.z));
        atomicMax(ob + 3 * NSEG + s, fmap(v.w));
    }
}

extern "C" void kernel_launch(void* const* d_in, const int* in_sizes, int n_in,
                              void* d_out, int out_size) {
    (void)in_sizes; (void)n_in;
    const float* feats = (const float*)d_in[0];
    const int*   mask  = (const int*)d_in[1];
    unsigned*    out   = (unsigned*)d_out;

    const int n = out_size;   // 8*64*512 = 262144

    sf_init_kernel<<<(n + 255) / 256, 256>>>(out, n);
    // pre-pass: 8*510*4 = 16320 warps, 8 warps/CTA -> 2040 CTAs
    sf_prep_kernel<<<(B_ * IROWS * 4 + 7) / 8, 256>>>(mask);
    sf_segmax_kernel<<<B_ * CGROUPS * SPLITS, THREADS>>>(feats, out);
    sf_fini_kernel<<<(n + 255) / 256, 256>>>(out, n);
}